// round 10
// baseline (speedup 1.0000x reference)
#include <cuda_runtime.h>
#include <cuda_bf16.h>
#include <cuda_fp16.h>
#include <cstdint>

// CuGraphSAGEConv pipeline (3 kernels):
//   K0 convert: x(f32) -> g_xh(fp16); W -> g_wcvt bf16 hi/lo
//   K1 gather:  WARP-PER-NODE mean of fp16 neighbors (no divergence),
//               writes full feat row incl. root-x bf16 hi/lo
//   K2 gemm:    multi-tile double-buffered cp.async + mma.sync 3-pass bf16

#define D_IN  64
#define DK    128
#define D_OUT 64

#define NPAD  100352
// feat row (512B): [agg_hi 128B | x_hi 128B | agg_lo 128B | x_lo 128B]
__device__ unsigned char g_feat[(size_t)NPAD * 512];
__device__ __half        g_xh[(size_t)NPAD * D_IN];
__device__ unsigned char g_wcvt[64 * 512];

// ======================= helpers =======================
__device__ __forceinline__ uint32_t smem_u32(const void* p) {
    uint32_t a;
    asm("{ .reg .u64 t; cvta.to.shared.u64 t, %1; cvt.u32.u64 %0, t; }"
        : "=r"(a) : "l"(p));
    return a;
}
__device__ __forceinline__ uint2 split2(float v0, float v1) {
    __nv_bfloat16 h0 = __float2bfloat16_rn(v0);
    __nv_bfloat16 h1 = __float2bfloat16_rn(v1);
    float r0 = v0 - __bfloat162float(h0);
    float r1 = v1 - __bfloat162float(h1);
    __nv_bfloat162 hh = __halves2bfloat162(h0, h1);
    __nv_bfloat162 ll = __halves2bfloat162(__float2bfloat16_rn(r0),
                                           __float2bfloat16_rn(r1));
    uint2 r;
    r.x = *reinterpret_cast<uint32_t*>(&hh);
    r.y = *reinterpret_cast<uint32_t*>(&ll);
    return r;
}
__device__ __forceinline__ void ldm_x4(uint4& r, uint32_t addr) {
    asm volatile("ldmatrix.sync.aligned.m8n8.x4.shared.b16 {%0,%1,%2,%3}, [%4];"
                 : "=r"(r.x), "=r"(r.y), "=r"(r.z), "=r"(r.w) : "r"(addr));
}
__device__ __forceinline__ void mma16816(float* c, const uint4& a,
                                         uint32_t b0, uint32_t b1) {
    asm volatile(
        "mma.sync.aligned.m16n8k16.row.col.f32.bf16.bf16.f32 "
        "{%0,%1,%2,%3}, {%4,%5,%6,%7}, {%8,%9}, {%0,%1,%2,%3};"
        : "+f"(c[0]), "+f"(c[1]), "+f"(c[2]), "+f"(c[3])
        : "r"(a.x), "r"(a.y), "r"(a.z), "r"(a.w), "r"(b0), "r"(b1));
}
__device__ __forceinline__ void cp16(uint32_t dst, const void* src) {
    asm volatile("cp.async.cg.shared.global [%0], [%1], 16;"
                 :: "r"(dst), "l"(src));
}
__device__ __forceinline__ __half2 u2h(uint32_t u) {
    return *reinterpret_cast<__half2*>(&u);
}

// ======================= K0: convert x and W =======================
__global__ __launch_bounds__(256)
void convert_kernel(const float4* __restrict__ x4,
                    const float4* __restrict__ W4,
                    int nx)   // nx = N*16 float4 elements of x
{
    const int idx = blockIdx.x * 256 + threadIdx.x;
    if (idx < nx) {
        float4 v = __ldg(x4 + idx);
        __half2 h01 = __floats2half2_rn(v.x, v.y);
        __half2 h23 = __floats2half2_rn(v.z, v.w);
        uint2 hp;
        hp.x = *reinterpret_cast<uint32_t*>(&h01);
        hp.y = *reinterpret_cast<uint32_t*>(&h23);
        reinterpret_cast<uint2*>(g_xh)[idx] = hp;
    } else if (idx >= nx && idx < nx + 2048) {
        const int c = idx - nx;               // 0..2047
        const int o = c >> 5;
        const int q = c & 31;
        float4 v = __ldg(W4 + c);
        uint2 p0 = split2(v.x, v.y);
        uint2 p1 = split2(v.z, v.w);
        unsigned char* wr = g_wcvt + (size_t)o * 512;
        *reinterpret_cast<uint2*>(wr + q * 8)       = make_uint2(p0.x, p1.x);
        *reinterpret_cast<uint2*>(wr + 256 + q * 8) = make_uint2(p0.y, p1.y);
    }
}

// ======================= K1: gather (warp per node) =======================
__global__ __launch_bounds__(256)
void gather_kernel(const float2* __restrict__ x2,
                   const int*    __restrict__ row,
                   const int*    __restrict__ colptr,
                   int N)
{
    const int g    = (blockIdx.x * 256 + threadIdx.x) >> 5;   // node = warp id
    const int lane = threadIdx.x & 31;
    if (g >= N) return;

    const uint32_t* xh = reinterpret_cast<const uint32_t*>(g_xh);  // 32 u32/row

    const int e0 = __ldg(colptr + g);
    const int e1 = __ldg(colptr + g + 1);

    float2 acc = make_float2(0.f, 0.f);

    int e = e0;
    if (e + 8 <= e1) {
        int s[8];
        #pragma unroll
        for (int j = 0; j < 8; j++) s[j] = __ldg(row + e + j);
        e += 8;
        while (true) {
            const bool more = (e + 8 <= e1);
            int t[8];
            if (more) {
                #pragma unroll
                for (int j = 0; j < 8; j++) t[j] = __ldg(row + e + j);
            }
            uint32_t v0 = __ldg(xh + (size_t)s[0] * 32 + lane);
            uint32_t v1 = __ldg(xh + (size_t)s[1] * 32 + lane);
            uint32_t v2 = __ldg(xh + (size_t)s[2] * 32 + lane);
            uint32_t v3 = __ldg(xh + (size_t)s[3] * 32 + lane);
            uint32_t v4 = __ldg(xh + (size_t)s[4] * 32 + lane);
            uint32_t v5 = __ldg(xh + (size_t)s[5] * 32 + lane);
            uint32_t v6 = __ldg(xh + (size_t)s[6] * 32 + lane);
            uint32_t v7 = __ldg(xh + (size_t)s[7] * 32 + lane);
            __half2 h = __hadd2(
                __hadd2(__hadd2(u2h(v0), u2h(v1)), __hadd2(u2h(v2), u2h(v3))),
                __hadd2(__hadd2(u2h(v4), u2h(v5)), __hadd2(u2h(v6), u2h(v7))));
            float2 f = __half22float2(h);
            acc.x += f.x;
            acc.y += f.y;
            if (!more) break;
            #pragma unroll
            for (int j = 0; j < 8; j++) s[j] = t[j];
            e += 8;
        }
    }
    for (; e < e1; e++) {
        int s = __ldg(row + e);
        uint32_t v = __ldg(xh + (size_t)s * 32 + lane);
        float2 f = __half22float2(u2h(v));
        acc.x += f.x;
        acc.y += f.y;
    }

    const int deg = e1 - e0;
    const float inv = 1.f / (float)(deg > 0 ? deg : 1);
    acc.x *= inv;
    acc.y *= inv;

    // root features (f32): lane holds elements 2*lane, 2*lane+1
    float2 rx = __ldg(x2 + (size_t)g * 32 + lane);

    uint2 pa = split2(acc.x, acc.y);
    uint2 px = split2(rx.x, rx.y);

    uint32_t* fr = reinterpret_cast<uint32_t*>(g_feat + (size_t)g * 512);
    fr[lane]      = pa.x;    // agg_hi [0,128)
    fr[32 + lane] = px.x;    // x_hi   [128,256)
    fr[64 + lane] = pa.y;    // agg_lo [256,384)
    fr[96 + lane] = px.y;    // x_lo   [384,512)
}

// ======================= K2: pipelined HMMA GEMM =======================
#define TB     64        // nodes per tile
#define ROWB   272
#define SM_WHI 0
#define SM_WLO 17408
#define SM_A0  34816     // buffer 0: [AHI 17408 | ALO 17408]
#define SM_A1  69632     // buffer 1
#define SM_TOT 104448
#define GRID2  296       // 2 CTAs/SM * 148

extern __shared__ char g_sm[];

__device__ __forceinline__ void stage_tile(uint32_t sb, int buf, int tbase, int tid)
{
    const uint32_t abase = sb + (buf ? SM_A1 : SM_A0);
    #pragma unroll
    for (int j = 0; j < 8; j++) {
        const int c   = tid + 256 * j;      // 0..2047
        const int r   = c >> 5;             // row 0..63
        const int q   = c & 31;             // 0..15 hi, 16..31 lo
        const unsigned char* src = g_feat + (size_t)(tbase + r) * 512 + q * 16;
        const uint32_t dst = abase + (q < 16 ? 0 : 17408)
                             + r * ROWB + (q & 15) * 16;
        cp16(dst, src);
    }
    asm volatile("cp.async.commit_group;" ::: "memory");
}

__global__ __launch_bounds__(256, 2)
void gemm_mma_kernel(const float* __restrict__ b,
                     float*       __restrict__ out,
                     int N, int ntiles)
{
    const uint32_t sb = smem_u32(g_sm);
    const int tid  = threadIdx.x;
    const int wid  = tid >> 5;
    const int lane = tid & 31;

    // ---- stage W (once per block) ----
    #pragma unroll
    for (int j = 0; j < 8; j++) {
        const int c = tid + 256 * j;
        const int o = c >> 5;
        const int q = c & 31;
        const unsigned char* src = g_wcvt + (size_t)o * 512 + q * 16;
        const uint32_t dst = sb + (q < 16 ? SM_WHI : SM_WLO)
                             + o * ROWB + (q & 15) * 16;
        cp16(dst, src);
    }
    asm volatile("cp.async.commit_group;" ::: "memory");

    int t0 = blockIdx.x;
    if (t0 < ntiles) stage_tile(sb, 0, t0 * TB, tid);

    const int wm = wid >> 1;
    const int wn = wid & 1;

    const uint32_t a_off = (uint32_t)(wm * 16 + (lane & 15)) * ROWB
                           + (uint32_t)(lane >> 4) * 16;
    const int brow = wn * 32 + ((lane >> 4) << 3) + (lane & 7);
    const uint32_t b_base = sb + SM_WHI
        + (uint32_t)brow * ROWB + (uint32_t)((lane >> 3) & 1) * 16;

    const int g   = lane >> 2;
    const int tig = lane & 3;
    float2 bb[4];
    #pragma unroll
    for (int ns = 0; ns < 4; ns++) {
        int col = wn * 32 + ns * 8 + 2 * tig;
        bb[ns] = make_float2(__ldg(b + col), __ldg(b + col + 1));
    }

    int i = 0;
    for (int t = t0; t < ntiles; t += GRID2, i++) {
        const int nxt = t + GRID2;
        if (nxt < ntiles) {
            stage_tile(sb, (i + 1) & 1, nxt * TB, tid);
            asm volatile("cp.async.wait_group 1;" ::: "memory");
        } else {
            asm volatile("cp.async.wait_group 0;" ::: "memory");
        }
        __syncthreads();

        const uint32_t a_base = sb + ((i & 1) ? SM_A1 : SM_A0) + a_off;

        float acc[4][4];
        #pragma unroll
        for (int ns = 0; ns < 4; ns++)
            #pragma unroll
            for (int q = 0; q < 4; q++) acc[ns][q] = 0.f;

        #pragma unroll
        for (int ks = 0; ks < 8; ks++) {
            const uint32_t ao = a_base + ks * 32;
            const uint32_t bo = b_base + ks * 32;
            uint4 ah, al, bh0, bh1, bl0, bl1;
            ldm_x4(ah, ao);
            ldm_x4(al, ao + 17408);
            ldm_x4(bh0, bo);
            ldm_x4(bh1, bo + 16 * ROWB);
            ldm_x4(bl0, bo + (SM_WLO - SM_WHI));
            ldm_x4(bl1, bo + (SM_WLO - SM_WHI) + 16 * ROWB);

            mma16816(acc[0], ah, bh0.x, bh0.y);
            mma16816(acc[1], ah, bh0.z, bh0.w);
            mma16816(acc[2], ah, bh1.x, bh1.y);
            mma16816(acc[3], ah, bh1.z, bh1.w);

            mma16816(acc[0], ah, bl0.x, bl0.y);
            mma16816(acc[1], ah, bl0.z, bl0.w);
            mma16816(acc[2], ah, bl1.x, bl1.y);
            mma16816(acc[3], ah, bl1.z, bl1.w);

            mma16816(acc[0], al, bh0.x, bh0.y);
            mma16816(acc[1], al, bh0.z, bh0.w);
            mma16816(acc[2], al, bh1.x, bh1.y);
            mma16816(acc[3], al, bh1.z, bh1.w);
        }

        const int node0 = t * TB + wm * 16 + g;
        const int node1 = node0 + 8;
        #pragma unroll
        for (int ns = 0; ns < 4; ns++) {
            const int col = wn * 32 + ns * 8 + 2 * tig;
            if (node0 < N)
                *reinterpret_cast<float2*>(out + (size_t)node0 * D_OUT + col) =
                    make_float2(acc[ns][0] + bb[ns].x, acc[ns][1] + bb[ns].y);
            if (node1 < N)
                *reinterpret_cast<float2*>(out + (size_t)node1 * D_OUT + col) =
                    make_float2(acc[ns][2] + bb[ns].x, acc[ns][3] + bb[ns].y);
        }
        __syncthreads();
    }
}

// ======================= launch =======================
extern "C" void kernel_launch(void* const* d_in, const int* in_sizes, int n_in,
                              void* d_out, int out_size)
{
    const float* x      = (const float*)d_in[0];
    const int*   row    = (const int*)  d_in[1];
    const int*   colptr = (const int*)  d_in[2];
    const float* W      = (const float*)d_in[3];
    const float* b      = (const float*)d_in[4];
    float*       out    = (float*)d_out;

    const int N = in_sizes[2] - 1;   // 100000
    const int ntiles = (N + TB - 1) / TB;

    cudaFuncSetAttribute(gemm_mma_kernel,
                         cudaFuncAttributeMaxDynamicSharedMemorySize, SM_TOT);

    const int nx = N * 16;
    convert_kernel<<<(nx + 2048 + 255) / 256, 256>>>(
        reinterpret_cast<const float4*>(x),
        reinterpret_cast<const float4*>(W), nx);

    gather_kernel<<<(N * 32 + 255) / 256, 256>>>(
        reinterpret_cast<const float2*>(x), row, colptr, N);

    gemm_mma_kernel<<<GRID2, 256, SM_TOT>>>(b, out, N, ntiles);
}